// round 16
// baseline (speedup 1.0000x reference)
#include <cuda_runtime.h>
#include <cuda_bf16.h>
#include <math.h>

#define B_   256
#define IN_  64
#define HID_ 128
#define OUT_ 64
#define T_   1000
#define CH_  10
#define CL_  100

// ---------------- device scratch (static, allocation-free) ----------------
__device__ float g_xeff[(size_t)B_ * IN_ * T_];   // (b, i, t) effective x
__device__ float g_gxT [(size_t)B_ * IN_ * T_];   // (b, n, t) gamma_x
// per (b,t): [0:128)=gamma_h  [128:256)=A_z  [256:384)=A_r  [384:512)=A_h
__device__ float g_act [(size_t)B_ * T_ * 512];
__device__ float g_wzrh[128 * 384];               // packed [x;m] -> [z|r|h]
__device__ float g_bzrh[384];
__device__ float g_lastx[B_ * IN_ * CH_];
__device__ float g_hasx [B_ * IN_ * CH_];

__device__ __forceinline__ float sigf(float x) { return 1.0f / (1.0f + __expf(-x)); }
__device__ __forceinline__ float tanhfast(float x) {
    float e = __expf(-2.0f * fabsf(x));
    float r = (1.0f - e) / (1.0f + e);
    return copysignf(r, x);
}
// packed f32x2 FMA (sm_10x)
__device__ __forceinline__ unsigned long long ffma2(unsigned long long a,
                                                    unsigned long long b,
                                                    unsigned long long c) {
    unsigned long long d;
    asm("fma.rn.f32x2 %0, %1, %2, %3;" : "=l"(d) : "l"(a), "l"(b), "l"(c));
    return d;
}
__device__ __forceinline__ unsigned long long pack2(float w) {
    unsigned long long d;
    asm("mov.b64 %0, {%1, %1};" : "=l"(d) : "f"(w));
    return d;
}
__device__ __forceinline__ float2 up2(unsigned long long u) {
    return make_float2(__uint_as_float((unsigned)u),
                       __uint_as_float((unsigned)(u >> 32)));
}

// ---------------- GEMM body (f32x2, 128x128 tile) ---------------------------
// C[b][t][n] = sum_f A[b][f][t] * W[f][n]  (+bias, +activation)
__device__ __forceinline__
void gemmT_body(const float* __restrict__ Ain,
                const float* __restrict__ W_in, int ldw, int Ncols,
                const float* __restrict__ bias_in,
                int K, int actMode, int outMode, int outOff, int srcMode,
                int n0, int t0, int b) {
    __shared__ __align__(16) float As[16 * 132];
    __shared__ __align__(16) float Bs[16 * 128];
    const float* Wp = srcMode ? g_wzrh : W_in;
    const float* bp = srcMode ? g_bzrh : bias_in;
    int tid = threadIdx.x;
    int f_l = tid >> 4, v = tid & 15;
    int ty  = tid >> 4, tx = tid & 15;

    unsigned long long acc[4][8];
#pragma unroll
    for (int i = 0; i < 4; i++)
#pragma unroll
        for (int j = 0; j < 8; j++) acc[i][j] = 0ull;

    for (int kbase = 0; kbase < K; kbase += 16) {
        int f = kbase + f_l;
        const float* rowp;
        if (srcMode == 0) {
            rowp = Ain + (size_t)2 * IN_ * T_ + (size_t)b * 3 * IN_ * T_ + (size_t)f * T_;
        } else {
            rowp = (f < 64) ? (g_xeff + (size_t)b * IN_ * T_ + (size_t)f * T_)
                            : (Ain + (size_t)IN_ * T_ + (size_t)b * 3 * IN_ * T_ + (size_t)(f - 64) * T_);
        }
#pragma unroll
        for (int h = 0; h < 2; ++h) {
            int tg = t0 + (v + 16 * h) * 4;
            float4 av = make_float4(0.f, 0.f, 0.f, 0.f);
            if (tg < T_) av = *(const float4*)(rowp + tg);
            *(float4*)&As[f_l * 132 + (v + 16 * h) * 4] = av;
        }
#pragma unroll
        for (int it = 0; it < 2; ++it) {
            int lin = tid + it * 256;
            int kq = lin >> 5, vq = lin & 31;
            int ng = n0 + vq * 4;
            float4 wv = make_float4(0.f, 0.f, 0.f, 0.f);
            if (ng < Ncols)
                wv = *(const float4*)(Wp + (size_t)(kbase + kq) * ldw + ng);
            *(float4*)&Bs[kq * 128 + vq * 4] = wv;
        }
        __syncthreads();
#pragma unroll
        for (int kk = 0; kk < 16; ++kk) {
            ulonglong2 a0 = *(const ulonglong2*)&As[kk * 132 + ty * 8];
            ulonglong2 a1 = *(const ulonglong2*)&As[kk * 132 + ty * 8 + 4];
            float4 bq0 = *(const float4*)&Bs[kk * 128 + tx * 8];
            float4 bq1 = *(const float4*)&Bs[kk * 128 + tx * 8 + 4];
            unsigned long long ap[4] = {a0.x, a0.y, a1.x, a1.y};
            unsigned long long bp8[8] = {pack2(bq0.x), pack2(bq0.y), pack2(bq0.z), pack2(bq0.w),
                                         pack2(bq1.x), pack2(bq1.y), pack2(bq1.z), pack2(bq1.w)};
#pragma unroll
            for (int i = 0; i < 4; i++)
#pragma unroll
                for (int j = 0; j < 8; j++) acc[i][j] = ffma2(ap[i], bp8[j], acc[i][j]);
        }
        __syncthreads();
    }
    if (n0 + tx * 8 >= Ncols) return;
    float bl[8];
#pragma unroll
    for (int j = 0; j < 8; j++) bl[j] = bp[n0 + tx * 8 + j];
#pragma unroll
    for (int ip = 0; ip < 4; ip++) {
        float va[2][8];
#pragma unroll
        for (int j = 0; j < 8; j++) {
            float2 c = up2(acc[ip][j]);
            va[0][j] = c.x; va[1][j] = c.y;
        }
#pragma unroll
        for (int s = 0; s < 2; ++s) {
            int tg = t0 + ty * 8 + ip * 2 + s;
            if (tg >= T_) continue;
            float vv[8];
#pragma unroll
            for (int j = 0; j < 8; j++) {
                float x = va[s][j] + bl[j];
                if (actMode == 1) x = __expf(-fmaxf(x, 0.0f));
                vv[j] = x;
            }
            if (outMode == 0) {
                float* dst = g_act + ((size_t)b * T_ + tg) * 512 + outOff + n0 + tx * 8;
                *(float4*)dst       = make_float4(vv[0], vv[1], vv[2], vv[3]);
                *(float4*)(dst + 4) = make_float4(vv[4], vv[5], vv[6], vv[7]);
            } else {
#pragma unroll
                for (int j = 0; j < 8; j++)
                    g_gxT[((size_t)b * 64 + n0 + tx * 8 + j) * T_ + tg] = vv[j];
            }
        }
    }
}

__global__ __launch_bounds__(256, 2)
void gemmT_kernel(const float* __restrict__ Ain,
                  const float* __restrict__ W_in, int ldw, int Ncols,
                  const float* __restrict__ bias_in,
                  int K, int actMode, int outMode, int outOff, int srcMode) {
    gemmT_body(Ain, W_in, ldw, Ncols, bias_in, K, actMode, outMode, outOff, srcMode,
               blockIdx.x * 128, blockIdx.y * 128, blockIdx.z);
}

// ---------------- merged: pack weights + LOCF chunk summaries --------------
__global__ void packScanA_kernel(const float* __restrict__ input,
                                 const float* __restrict__ Wxz, const float* __restrict__ Wmz,
                                 const float* __restrict__ bmz,
                                 const float* __restrict__ Wxr, const float* __restrict__ Wmr,
                                 const float* __restrict__ Wxh, const float* __restrict__ Wmh,
                                 const float* __restrict__ bmh) {
    if (blockIdx.x < 32) {
        int tid0 = blockIdx.x * 256 + threadIdx.x;
        const int stride = 32 * 256;
        for (int idx = tid0; idx < 128 * 384; idx += stride) {
            int k = idx / 384, n = idx % 384;
            int mat = n >> 7, j = n & 127;
            const float* Wx = (mat == 0) ? Wxz : ((mat == 1) ? Wxr : Wxh);
            const float* Wm = (mat == 0) ? Wmz : ((mat == 1) ? Wmr : Wmh);
            g_wzrh[idx] = (k < 64) ? Wx[k * 128 + j] : Wm[(k - 64) * 128 + j];
        }
        for (int n = tid0; n < 384; n += stride) {
            int mat = n >> 7, j = n & 127;
            g_bzrh[n] = (mat == 0) ? bmz[j] : ((mat == 2) ? bmh[j] : 0.0f);
        }
    } else {
        int tid = (blockIdx.x - 32) * 256 + threadIdx.x;   // < B*IN*CH
        int c = tid % CH_;
        int bi = tid / CH_;
        int b = bi >> 6, i = bi & 63;
        const float4* Xp = (const float4*)(input + ((size_t)(b * 3 + 0) * IN_ + i) * T_ + c * CL_);
        const float4* Mp = (const float4*)(input + ((size_t)(b * 3 + 1) * IN_ + i) * T_ + c * CL_);
        float last = 0.f, has = 0.f;
#pragma unroll 5
        for (int v = 0; v < CL_ / 4; ++v) {
            float4 x4 = Xp[v], m4 = Mp[v];
            if (m4.x > 0.f) { last = x4.x; has = 1.f; }
            if (m4.y > 0.f) { last = x4.y; has = 1.f; }
            if (m4.z > 0.f) { last = x4.z; has = 1.f; }
            if (m4.w > 0.f) { last = x4.w; has = 1.f; }
        }
        g_lastx[tid] = last;
        g_hasx[tid] = has;
    }
}

// ---------------- merged: gamma_h GEMM + LOCF apply (scanB) ----------------
__global__ __launch_bounds__(256, 2)
void ghScanB_kernel(const float* __restrict__ input,
                    const float* __restrict__ Wdgh, const float* __restrict__ bdgh,
                    const float* __restrict__ x_mean) {
    if (blockIdx.x < 2048) {
        gemmT_body(input, Wdgh, 128, 128, bdgh, 64, /*act*/1, /*out*/0, 0, /*src*/0,
                   /*n0*/0, /*t0*/(blockIdx.x & 7) * 128, /*b*/blockIdx.x >> 3);
    } else {
        int tid = (blockIdx.x - 2048) * 256 + threadIdx.x;
        int c = tid % CH_;
        int bi = tid / CH_;
        int b = bi >> 6, i = bi & 63;
        float xl = 0.f;
        for (int cc = c - 1; cc >= 0; --cc) {
            if (g_hasx[bi * CH_ + cc] > 0.f) { xl = g_lastx[bi * CH_ + cc]; break; }
        }
        const float4* Xp = (const float4*)(input + ((size_t)(b * 3 + 0) * IN_ + i) * T_ + c * CL_);
        const float4* Mp = (const float4*)(input + ((size_t)(b * 3 + 1) * IN_ + i) * T_ + c * CL_);
        const float4* Gp = (const float4*)(g_gxT + ((size_t)b * IN_ + i) * T_ + c * CL_);
        float4*       Op = (float4*)(g_xeff + ((size_t)b * IN_ + i) * T_ + c * CL_);
        float xm = x_mean[i];
#pragma unroll 5
        for (int v = 0; v < CL_ / 4; ++v) {
            float4 x4 = Xp[v], m4 = Mp[v], g4 = Gp[v];
            float4 o;
            if (m4.x > 0.f) { xl = x4.x; o.x = x4.x; } else { o.x = g4.x * xl + (1.f - g4.x) * xm; }
            if (m4.y > 0.f) { xl = x4.y; o.y = x4.y; } else { o.y = g4.y * xl + (1.f - g4.y) * xm; }
            if (m4.z > 0.f) { xl = x4.z; o.z = x4.z; } else { o.z = g4.z * xl + (1.f - g4.z) * xm; }
            if (m4.w > 0.f) { xl = x4.w; o.w = x4.w; } else { o.w = g4.w * xl + (1.f - g4.w) * xm; }
            Op[v] = o;
        }
    }
}

// ---------------- recurrence + fused y: gate-split, 2 warps/SMSP -----------
// 256 threads, 128 CTAs (2 batch rows each).
//   group Z (tid<128, col j): hh, z-GEMV, h~-GEMV, h update, hs store
//   group R (tid>=128, col j): r-GEMV + hp write; then y-GEMV for step t-1
// Weights Wz/Wr/Wh fp32 in smem (each read by exactly one group -> crossbar
// bytes unchanged vs R13). Why stored bf16 in smem (y has no recurrence, so
// bf16 error ~1e-4 stays well under 1e-3). h history double-buffered in smem.
__global__ __launch_bounds__(256, 1)
void recur_kernel(const float* __restrict__ Whz, const float* __restrict__ Whr,
                  const float* __restrict__ Whh, const float* __restrict__ Why,
                  const float* __restrict__ bhy, float* __restrict__ out) {
    extern __shared__ float sm[];
    float* Wz    = sm;                    // 128*132
    float* Wr    = Wz + 128 * 132;        // 128*132
    float* Wh    = Wr + 128 * 132;        // 128*132
    float* hbuf  = Wh + 128 * 132;        // 2 bufs x 2 rows x 128
    float* rbuf  = hbuf + 512;            // 2 bufs x 2 rows x 128
    float* hhist = rbuf + 512;            // 2 bufs x 2 rows x 128
    float* bys   = hhist + 512;           // 64
    __nv_bfloat16* WyT = (__nv_bfloat16*)(bys + 64);  // 64 cols x 136 (bf16)

    int tid = threadIdx.x;
    int j = tid & 127;
    bool isZ = tid < 128;
    int b0 = blockIdx.x * 2, b1 = b0 + 1;

    // load weights (transposed) into smem
    for (int idx = tid; idx < 128 * 128; idx += 256) {
        int k = idx >> 7, jj = idx & 127;
        Wz[jj * 132 + k] = Whz[idx];
        Wr[jj * 132 + k] = Whr[idx];
        Wh[jj * 132 + k] = Whh[idx];
    }
    // Why -> bf16, column-major with stride 136 (16B-aligned, conflict-free)
    for (int idx = tid; idx < 64 * 128; idx += 256) {
        int c = idx >> 7, k = idx & 127;
        WyT[c * 136 + k] = __float2bfloat16(Why[k * 64 + c]);
    }
    if (tid < 64) bys[tid] = bhy[tid];
    __syncthreads();

    float* hs = out + (size_t)B_ * T_ * OUT_;

    const float* act0 = g_act + (size_t)b0 * T_ * 512 + j;
    const float* act1 = act0 + (size_t)T_ * 512;

    // per-group state
    float h0 = 0.f, h1 = 0.f, hh0 = 0.f, hh1 = 0.f;
    float gh0 = 0.f, az0 = 0.f, ah0 = 0.f, gh1 = 0.f, az1 = 0.f, ah1 = 0.f;
    float ar0 = 0.f, ar1 = 0.f;
    if (isZ) {
        gh0 = act0[0]; az0 = act0[128]; ah0 = act0[384];
        gh1 = act1[0]; az1 = act1[128]; ah1 = act1[384];
    } else {
        ar0 = act0[256]; ar1 = act1[256];
    }

    const float4* wz4 = (const float4*)(Wz + j * 132);
    const float4* wr4 = (const float4*)(Wr + j * 132);
    const float4* wh4 = (const float4*)(Wh + j * 132);

    int yc = j & 63, yrow = j >> 6;
    const uint4* wyc = (const uint4*)(WyT + yc * 136);
    float ybias = bys[yc];
    float* yout0 = out + ((size_t)(b0 + yrow) * T_) * 64 + yc;

    for (int t = 0; t < T_; ++t) {
        int p = t & 1;
        float* hq = hbuf + p * 256;
        float* hp = rbuf + p * 256;

        if (isZ) {
            hh0 = gh0 * h0;
            hh1 = gh1 * h1;
            hq[j] = hh0;
            hq[128 + j] = hh1;
        }

        // prefetch next-step activations (per group)
        float ngh0 = gh0, naz0 = az0, nah0 = ah0;
        float ngh1 = gh1, naz1 = az1, nah1 = ah1;
        float nar0 = ar0, nar1 = ar1;
        if (t + 1 < T_) {
            if (isZ) {
                const float* a0 = act0 + (size_t)(t + 1) * 512;
                const float* a1 = act1 + (size_t)(t + 1) * 512;
                ngh0 = a0[0]; naz0 = a0[128]; nah0 = a0[384];
                ngh1 = a1[0]; naz1 = a1[128]; nah1 = a1[384];
            } else {
                nar0 = act0[(size_t)(t + 1) * 512 + 256];
                nar1 = act1[(size_t)(t + 1) * 512 + 256];
            }
        }
        __syncthreads();   // hq ready

        float z0 = 0.f, z1 = 0.f;
        const float4* h0v = (const float4*)hq;
        const float4* h1v = (const float4*)(hq + 128);
        if (isZ) {
            // z-GEMV: 8 chains
            float za0 = az0, zb0 = 0.f, zc0 = 0.f, zd0 = 0.f;
            float za1 = az1, zb1 = 0.f, zc1 = 0.f, zd1 = 0.f;
#pragma unroll
            for (int k4 = 0; k4 < 32; ++k4) {
                float4 wz = wz4[k4];
                float4 a0 = h0v[k4], a1 = h1v[k4];
                za0 = fmaf(wz.x, a0.x, za0); zb0 = fmaf(wz.y, a0.y, zb0);
                zc0 = fmaf(wz.z, a0.z, zc0); zd0 = fmaf(wz.w, a0.w, zd0);
                za1 = fmaf(wz.x, a1.x, za1); zb1 = fmaf(wz.y, a1.y, zb1);
                zc1 = fmaf(wz.z, a1.z, zc1); zd1 = fmaf(wz.w, a1.w, zd1);
            }
            z0 = sigf((za0 + zb0) + (zc0 + zd0));
            z1 = sigf((za1 + zb1) + (zc1 + zd1));
        } else {
            // r-GEMV: 8 chains, then hp = r * hh
            float ra0 = ar0, rb0 = 0.f, rc0 = 0.f, rd0 = 0.f;
            float ra1 = ar1, rb1 = 0.f, rc1 = 0.f, rd1 = 0.f;
#pragma unroll
            for (int k4 = 0; k4 < 32; ++k4) {
                float4 wr = wr4[k4];
                float4 a0 = h0v[k4], a1 = h1v[k4];
                ra0 = fmaf(wr.x, a0.x, ra0); rb0 = fmaf(wr.y, a0.y, rb0);
                rc0 = fmaf(wr.z, a0.z, rc0); rd0 = fmaf(wr.w, a0.w, rd0);
                ra1 = fmaf(wr.x, a1.x, ra1); rb1 = fmaf(wr.y, a1.y, rb1);
                rc1 = fmaf(wr.z, a1.z, rc1); rd1 = fmaf(wr.w, a1.w, rd1);
            }
            float r0 = sigf((ra0 + rb0) + (rc0 + rd0));
            float r1 = sigf((ra1 + rb1) + (rc1 + rd1));
            hp[j] = r0 * hq[j];
            hp[128 + j] = r1 * hq[128 + j];
        }
        __syncthreads();   // hp ready; hhist[t-1] still valid

        if (isZ) {
            // h_tilde GEMV: 8 chains
            float ta0 = ah0, tb0 = 0.f, tc0 = 0.f, td0 = 0.f;
            float ta1 = ah1, tb1 = 0.f, tc1 = 0.f, td1 = 0.f;
            const float4* p0v = (const float4*)hp;
            const float4* p1v = (const float4*)(hp + 128);
#pragma unroll
            for (int k4 = 0; k4 < 32; ++k4) {
                float4 wh = wh4[k4];
                float4 a0 = p0v[k4], a1 = p1v[k4];
                ta0 = fmaf(wh.x, a0.x, ta0); tb0 = fmaf(wh.y, a0.y, tb0);
                tc0 = fmaf(wh.z, a0.z, tc0); td0 = fmaf(wh.w, a0.w, td0);
                ta1 = fmaf(wh.x, a1.x, ta1); tb1 = fmaf(wh.y, a1.y, tb1);
                tc1 = fmaf(wh.z, a1.z, tc1); td1 = fmaf(wh.w, a1.w, td1);
            }
            float ht0 = tanhfast((ta0 + tb0) + (tc0 + td0));
            float ht1 = tanhfast((ta1 + tb1) + (tc1 + td1));
            h0 = (1.f - z0) * hh0 + z0 * ht0;
            h1 = (1.f - z1) * hh1 + z1 * ht1;
            hs[((size_t)b0 * T_ + t) * 128 + j] = h0;
            hs[((size_t)b1 * T_ + t) * 128 + j] = h1;
            float* hd = hhist + p * 256;
            hd[j] = h0;
            hd[128 + j] = h1;
            gh0 = ngh0; az0 = naz0; ah0 = nah0;
            gh1 = ngh1; az1 = naz1; ah1 = nah1;
        } else {
            if (t > 0) {
                // y_{t-1} = sigmoid(h_{t-1} @ Why + bhy), Why in bf16
                const float4* hr4 = (const float4*)(hhist + ((t - 1) & 1) * 256 + yrow * 128);
                float ya = ybias, yb2 = 0.f, yc2 = 0.f, yd2 = 0.f;
#pragma unroll
                for (int q = 0; q < 16; ++q) {
                    uint4 w = wyc[q];
                    float4 hA = hr4[2 * q];
                    float4 hB = hr4[2 * q + 1];
                    float2 f0 = __bfloat1622float2(*(const __nv_bfloat162*)&w.x);
                    float2 f1 = __bfloat1622float2(*(const __nv_bfloat162*)&w.y);
                    float2 f2 = __bfloat1622float2(*(const __nv_bfloat162*)&w.z);
                    float2 f3 = __bfloat1622float2(*(const __nv_bfloat162*)&w.w);
                    ya  = fmaf(f0.x, hA.x, ya);  yb2 = fmaf(f0.y, hA.y, yb2);
                    yc2 = fmaf(f1.x, hA.z, yc2); yd2 = fmaf(f1.y, hA.w, yd2);
                    ya  = fmaf(f2.x, hB.x, ya);  yb2 = fmaf(f2.y, hB.y, yb2);
                    yc2 = fmaf(f3.x, hB.z, yc2); yd2 = fmaf(f3.y, hB.w, yd2);
                }
                yout0[(size_t)(t - 1) * 64] = sigf((ya + yb2) + (yc2 + yd2));
            }
            ar0 = nar0; ar1 = nar1;
        }
    }

    __syncthreads();
    if (!isZ) {
        // tail: y_{T-1}
        const float4* hr4 = (const float4*)(hhist + ((T_ - 1) & 1) * 256 + yrow * 128);
        float ya = ybias, yb2 = 0.f, yc2 = 0.f, yd2 = 0.f;
#pragma unroll
        for (int q = 0; q < 16; ++q) {
            uint4 w = wyc[q];
            float4 hA = hr4[2 * q];
            float4 hB = hr4[2 * q + 1];
            float2 f0 = __bfloat1622float2(*(const __nv_bfloat162*)&w.x);
            float2 f1 = __bfloat1622float2(*(const __nv_bfloat162*)&w.y);
            float2 f2 = __bfloat1622float2(*(const __nv_bfloat162*)&w.z);
            float2 f3 = __bfloat1622float2(*(const __nv_bfloat162*)&w.w);
            ya  = fmaf(f0.x, hA.x, ya);  yb2 = fmaf(f0.y, hA.y, yb2);
            yc2 = fmaf(f1.x, hA.z, yc2); yd2 = fmaf(f1.y, hA.w, yd2);
            ya  = fmaf(f2.x, hB.x, ya);  yb2 = fmaf(f2.y, hB.y, yb2);
            yc2 = fmaf(f3.x, hB.z, yc2); yd2 = fmaf(f3.y, hB.w, yd2);
        }
        yout0[(size_t)(T_ - 1) * 64] = sigf((ya + yb2) + (yc2 + yd2));
    }
}

// ---------------- launch ----------------------------------------------------
extern "C" void kernel_launch(void* const* d_in, const int* in_sizes, int n_in,
                              void* d_out, int out_size) {
    const float* input  = (const float*)d_in[0];
    const float* x_mean = (const float*)d_in[1];
    const float* W_dg_x = (const float*)d_in[2];
    const float* b_dg_x = (const float*)d_in[3];
    const float* W_dg_h = (const float*)d_in[4];
    const float* b_dg_h = (const float*)d_in[5];
    const float* W_xz   = (const float*)d_in[6];
    const float* W_hz   = (const float*)d_in[7];
    const float* W_mz   = (const float*)d_in[8];
    const float* b_mz   = (const float*)d_in[9];
    const float* W_xr   = (const float*)d_in[10];
    const float* W_hr   = (const float*)d_in[11];
    const float* W_mr   = (const float*)d_in[12];
    const float* W_xh   = (const float*)d_in[13];
    const float* W_hh   = (const float*)d_in[14];
    const float* W_mh   = (const float*)d_in[15];
    const float* b_mh   = (const float*)d_in[16];
    const float* W_hy   = (const float*)d_in[17];
    const float* b_hy   = (const float*)d_in[18];
    float* out = (float*)d_out;

    // Wz/Wr/Wh + hbuf/rbuf/hhist + bys + WyT(bf16)
    const int recur_smem = (3 * 128 * 132 + 3 * 512 + 64) * 4 + 64 * 136 * 2;  // 226560

    static bool attr_set = false;
    if (!attr_set) {
        cudaFuncSetAttribute(recur_kernel, cudaFuncAttributeMaxDynamicSharedMemorySize,
                             recur_smem);
        attr_set = true;
    }

    // k1: pack combined weights + LOCF chunk summaries
    packScanA_kernel<<<32 + (B_ * IN_ * CH_) / 256, 256>>>(
        input, W_xz, W_mz, b_mz, W_xr, W_mr, W_xh, W_mh, b_mh);

    // k2: gamma_x GEMM: K=64, N=64 -> g_gxT (b,n,t)
    gemmT_kernel<<<dim3(1, 8, B_), 256>>>(input, W_dg_x, 64, 64, b_dg_x,
                                          64, /*act*/1, /*out*/1, 0, /*src*/0);

    // k3: gamma_h GEMM + LOCF apply
    ghScanB_kernel<<<2048 + (B_ * IN_ * CH_) / 256, 256>>>(input, W_dg_h, b_dg_h, x_mean);

    // k4: A_zrh GEMM: K=128, N=384 -> g_act[128:512)
    gemmT_kernel<<<dim3(3, 8, B_), 256>>>(input, nullptr, 384, 384, nullptr,
                                          128, 0, 0, 128, 1);

    // k5: recurrence + fused y -> both regions of d_out
    recur_kernel<<<128, 256, recur_smem>>>(W_hz, W_hr, W_hh, W_hy, b_hy, out);
}